// round 10
// baseline (speedup 1.0000x reference)
#include <cuda_runtime.h>
#include <cuda_bf16.h>
#include <cstdint>

#define BATCH 4
#define NPTS  4096
#define DIM   64
#define LOG2E 1.4426950408889634f
#define SC_F  24.0224478f          // sqrt(log2e)/0.05
#define TWOL  2.8853900817779268f  // 2*log2e

#define BM 64
#define BN 64
#define NJT (NPTS/BN)   // 64
#define NIT (NPTS/BM)   // 64

#define ROWB 272                    // 256B packed row + 16B pad
#define OFF_A 0
#define SZ_A  (64*ROWB)             // 17408
#define OFF_B (SZ_A)                // 17408
#define SZ_B  (64*ROWB)             // 17408
#define OFF_P (OFF_B + 2*SZ_B)      // 52224
#define SZ_P  1280                  // [0,1024) float4 xj ; [1024,1280) cn2
#define OFF_M (OFF_P + 4*SZ_P)      // 57344 ; 64 rows x 6 floats
#define OFF_R (OFF_M + 64*6*4)      // 58880
#define SMEM_TOTAL (OFF_R + 64)     // 58944

// scratch (no allocation allowed)
__device__ __align__(16) uint32_t g_pk1[BATCH*NPTS*64]; // [hi64|lo64] bf16, f1*2log2e
__device__ __align__(16) uint32_t g_pk2[BATCH*NPTS*64]; // [hi64|lo64] bf16, f2 raw
__device__ __align__(16) float4   g_pi[BATCH*NPTS];     // xi*SC
__device__ __align__(16) float4   g_pj[BATCH*NPTS];     // xj*SC, w = -|xj|^2
__device__ __align__(16) float    g_cn2[BATCH*NPTS];    // log2e*|f2|^2
__device__ float g_partial[BATCH*NIT];

__device__ __forceinline__ float ex2(float x){
    float y; asm("ex2.approx.ftz.f32 %0, %1;" : "=f"(y) : "f"(x)); return y;
}
__device__ __forceinline__ void cpa16(uint32_t dst, const void* src){
    asm volatile("cp.async.cg.shared.global [%0], [%1], 16;\n" :: "r"(dst), "l"(src));
}
__device__ __forceinline__ void ldmx4(uint32_t& r0,uint32_t& r1,uint32_t& r2,uint32_t& r3, uint32_t a){
    asm volatile("ldmatrix.sync.aligned.m8n8.x4.shared.b16 {%0,%1,%2,%3}, [%4];\n"
                 : "=r"(r0),"=r"(r1),"=r"(r2),"=r"(r3) : "r"(a));
}
__device__ __forceinline__ void mma16816(float* c, const uint32_t* a, uint32_t b0, uint32_t b1){
    asm volatile("mma.sync.aligned.m16n8k16.row.col.f32.bf16.bf16.f32 "
                 "{%0,%1,%2,%3}, {%4,%5,%6,%7}, {%8,%9}, {%0,%1,%2,%3};\n"
                 : "+f"(c[0]),"+f"(c[1]),"+f"(c[2]),"+f"(c[3])
                 : "r"(a[0]),"r"(a[1]),"r"(a[2]),"r"(a[3]), "r"(b0),"r"(b1));
}

// ---------------------------------------------------------------------------
__global__ void prep_kernel(const float* __restrict__ pts,
                            const float* __restrict__ f1,
                            const float* __restrict__ f2)
{
    int gw   = (blockIdx.x*blockDim.x + threadIdx.x) >> 5;
    int lane = threadIdx.x & 31;
    if (gw >= BATCH*NPTS) return;
    const float* r1 = f1 + (size_t)gw*DIM;
    const float* r2 = f2 + (size_t)gw*DIM;
    float a0 = r1[lane], a1 = r1[lane+32];
    float b0 = r2[lane], b1 = r2[lane+32];
    float n2 = b0*b0 + b1*b1;
    #pragma unroll
    for (int o=16;o>=1;o>>=1) n2 += __shfl_xor_sync(~0u,n2,o);

    float s0 = a0*TWOL, s1 = a1*TWOL;
    __nv_bfloat16 h0=__float2bfloat16(s0), h1=__float2bfloat16(s1);
    __nv_bfloat16 l0=__float2bfloat16(s0-__bfloat162float(h0));
    __nv_bfloat16 l1=__float2bfloat16(s1-__bfloat162float(h1));
    __nv_bfloat16* o1 = (__nv_bfloat16*)(g_pk1 + (size_t)gw*64);
    o1[lane]=h0; o1[32+lane]=h1; o1[64+lane]=l0; o1[96+lane]=l1;

    __nv_bfloat16 H0=__float2bfloat16(b0), H1=__float2bfloat16(b1);
    __nv_bfloat16 L0=__float2bfloat16(b0-__bfloat162float(H0));
    __nv_bfloat16 L1=__float2bfloat16(b1-__bfloat162float(H1));
    __nv_bfloat16* o2 = (__nv_bfloat16*)(g_pk2 + (size_t)gw*64);
    o2[lane]=H0; o2[32+lane]=H1; o2[64+lane]=L0; o2[96+lane]=L1;

    if (lane==0){
        float px = pts[(size_t)gw*3+0]*SC_F;
        float py = pts[(size_t)gw*3+1]*SC_F;
        float pz = pts[(size_t)gw*3+2]*SC_F;
        g_pi[gw]  = make_float4(px,py,pz,0.0f);
        g_pj[gw]  = make_float4(px,py,pz, -fmaf(px,px, fmaf(py,py, pz*pz)));
        g_cn2[gw] = n2*LOG2E;
    }
}

// ---------------------------------------------------------------------------
__device__ __forceinline__ void load_B_tile(uint32_t sb, int tid, int b, int jt){
    const char* gB = (const char*)(g_pk2 + (size_t)(b*NPTS + jt*BN)*64);
    const uint32_t dst = sb + OFF_B + (jt&1)*SZ_B;
    #pragma unroll
    for(int q=0;q<4;q++){
        int idx=q*256+tid, r=idx>>4, c=idx&15;
        cpa16(dst + r*ROWB + c*16, gB + r*256 + c*16);
    }
    const uint32_t pdst = sb + OFF_P + (jt&3)*SZ_P;
    const int j0 = jt*BN;
    if (tid<64) cpa16(pdst + tid*16, (const char*)(g_pj + b*NPTS + j0 + tid));
    else if (tid<80) cpa16(pdst + 1024 + (tid-64)*16,
                           (const char*)(g_cn2 + b*NPTS + j0 + (tid-64)*4));
}

// ---------------------------------------------------------------------------
// 256 thr = 8 warps: wm=w&3 (row band of 16), wn=w>>2 (col band of 32).
// Warp tile 16 rows x 32 cols; A fragments held in registers across all tiles.
// ---------------------------------------------------------------------------
__global__ __launch_bounds__(256,2)
void loss_kernel(const float* __restrict__ wts)
{
    extern __shared__ __align__(16) char smem[];
    const uint32_t sb = (uint32_t)__cvta_generic_to_shared(smem);
    const int b  = blockIdx.y;
    const int i0 = blockIdx.x*BM;
    const int tid = threadIdx.x;
    const int w = tid>>5, lane = tid&31;
    const int wm = w&3, wn = w>>2;
    const int g = lane>>2, tig = lane&3;

    // prologue: A + B0 + P0 (group0), B1 + P1 (group1)
    {
        const char* gA = (const char*)(g_pk1 + (size_t)(b*NPTS+i0)*64);
        #pragma unroll
        for(int q=0;q<4;q++){
            int idx=q*256+tid, r=idx>>4, c=idx&15;
            cpa16(sb + OFF_A + r*ROWB + c*16, gA + r*256 + c*16);
        }
        load_B_tile(sb, tid, b, 0);
        asm volatile("cp.async.commit_group;\n");
        load_B_tile(sb, tid, b, 1);
        asm volatile("cp.async.commit_group;\n");
    }

    const uint32_t aAddr = sb + OFF_A + (wm*16 + (lane&15))*ROWB + (lane>>4)*16;
    const int bn_row = (lane&7) + (((lane>>4)&1)<<3);
    const uint32_t bk16 = ((lane>>3)&1)*16;

    // per-thread rows: r0 = wm*16+g, r1 = r0+8
    float x2x[2],x2y[2],x2z[2],nni[2];
    #pragma unroll
    for(int h=0;h<2;h++){
        int rl = wm*16 + g + h*8;
        float4 v = g_pi[b*NPTS + i0 + rl];
        x2x[h]=v.x+v.x; x2y[h]=v.y+v.y; x2z[h]=v.z+v.z;
        nni[h]=-fmaf(v.x,v.x, fmaf(v.y,v.y, v.z*v.z));
    }
    float m2[2],Z1[2],Z2[2],Av[2],Bv[2],Cv[2];
    #pragma unroll
    for(int h=0;h<2;h++){ m2[h]=-3.0e38f; Z1[h]=0.f;Z2[h]=0.f;Av[h]=0.f;Bv[h]=0.f;Cv[h]=0.f; }

    asm volatile("cp.async.wait_group 1;\n" ::: "memory");
    __syncthreads();

    // hoist A fragments (hi and lo) into registers: 8 ldmatrix.x4 = 32 regs
    uint32_t ah[4][4], al[4][4];
    #pragma unroll
    for(int c=0;c<4;c++){
        ldmx4(ah[c][0],ah[c][1],ah[c][2],ah[c][3], aAddr + c*32);
        ldmx4(al[c][0],al[c][1],al[c][2],al[c][3], aAddr + 128 + c*32);
    }

    for(int jt=0; jt<NJT; jt++){
        const int buf = jt&1;
        // ---- MMA: 4 k16-chunks x {HH,HL,LH}; B-only ldmatrix (16 per tile) ----
        float acc[4][4];
        #pragma unroll
        for(int nb=0;nb<4;nb++)
            #pragma unroll
            for(int q=0;q<4;q++) acc[nb][q]=0.f;
        #pragma unroll
        for(int c=0;c<4;c++){
            #pragma unroll
            for(int n2=0;n2<2;n2++){
                uint32_t ba = sb + OFF_B + buf*SZ_B
                            + (wn*32 + n2*16 + bn_row)*ROWB + bk16;
                uint32_t bh[4], bl[4];
                ldmx4(bh[0],bh[1],bh[2],bh[3], ba + c*32);
                ldmx4(bl[0],bl[1],bl[2],bl[3], ba + 128 + c*32);
                mma16816(acc[n2*2+0], ah[c], bh[0], bh[1]);
                mma16816(acc[n2*2+1], ah[c], bh[2], bh[3]);
                mma16816(acc[n2*2+0], ah[c], bl[0], bl[1]);
                mma16816(acc[n2*2+1], ah[c], bl[2], bl[3]);
                mma16816(acc[n2*2+0], al[c], bh[0], bh[1]);
                mma16816(acc[n2*2+1], al[c], bh[2], bh[3]);
            }
        }

        // sync off the B buffer we just read, then prefetch jt+2 into it
        if (jt+1 < NJT){
            asm volatile("cp.async.wait_group 0;\n" ::: "memory");
        }
        __syncthreads();
        if (jt+2 < NJT){
            load_B_tile(sb, tid, b, jt+2);
            asm volatile("cp.async.commit_group;\n");
        }

        // ---- epilogue on current tile ----
        {
            const float4* pP = (const float4*)(smem + OFF_P + (jt&3)*SZ_P);
            const float*  pC = (const float*) (smem + OFF_P + (jt&3)*SZ_P + 1024);
            // cache my 8 cn2 values; per-tile safe rescale bound
            float cn2v[8];
            float mn = 3.0e38f;
            #pragma unroll
            for(int nb=0;nb<4;nb++)
                #pragma unroll
                for(int q=0;q<2;q++){
                    int c = wn*32 + nb*8 + tig*2 + q;
                    cn2v[nb*2+q] = pC[c];
                    mn = fminf(mn, cn2v[nb*2+q]);
                }
            #pragma unroll
            for(int h=0;h<2;h++){
                float mx = -3.0e38f;
                #pragma unroll
                for(int nb=0;nb<4;nb++)
                    mx = fmaxf(mx, fmaxf(acc[nb][h*2], acc[nb][h*2+1]));
                float m2n = fmaxf(m2[h], mx - mn);
                float c2 = ex2(m2[h] - m2n);
                Z2[h]*=c2; Cv[h]*=c2; Bv[h]*=c2*c2; m2[h]=m2n;
            }
            #pragma unroll
            for(int nb=0;nb<4;nb++){
                #pragma unroll
                for(int q=0;q<2;q++){
                    int c = wn*32 + nb*8 + tig*2 + q;
                    float4 v = pP[c];
                    float cn = cn2v[nb*2+q];
                    #pragma unroll
                    for(int h=0;h<2;h++){
                        float e2 = ex2((acc[nb][h*2+q] - cn) - m2[h]);
                        float tt = fmaf(x2x[h], v.x, fmaf(x2y[h], v.y,
                                   fmaf(x2z[h], v.z, v.w))) + nni[h];
                        float e1 = ex2(tt);
                        Z1[h]+=e1; Av[h]=fmaf(e1,e1,Av[h]);
                        Z2[h]+=e2; Bv[h]=fmaf(e2,e2,Bv[h]);
                        Cv[h]=fmaf(e1,e2,Cv[h]);
                    }
                }
            }
        }
    }

    // ---- merge 4 tig-lanes per row ----
    #pragma unroll
    for(int h=0;h<2;h++){
        #pragma unroll
        for(int off=1; off<=2; off<<=1){
            float om = __shfl_xor_sync(~0u, m2[h], off);
            float oZ2= __shfl_xor_sync(~0u, Z2[h], off);
            float oB = __shfl_xor_sync(~0u, Bv[h], off);
            float oC = __shfl_xor_sync(~0u, Cv[h], off);
            float oZ1= __shfl_xor_sync(~0u, Z1[h], off);
            float oA = __shfl_xor_sync(~0u, Av[h], off);
            float nm = fmaxf(m2[h], om);
            float c = ex2(m2[h]-nm), d = ex2(om-nm);
            Z2[h]=Z2[h]*c + oZ2*d;
            Bv[h]=Bv[h]*c*c + oB*d*d;
            Cv[h]=Cv[h]*c + oC*d;
            Z1[h]+=oZ1; Av[h]+=oA;
            m2[h]=nm;
        }
    }
    // ---- merge the two wn col-bands via smem ----
    float* sM = (float*)(smem + OFF_M);
    float* sR = (float*)(smem + OFF_R);
    if (wn==1 && tig==0){
        #pragma unroll
        for(int h=0;h<2;h++){
            int rl = wm*16 + g + h*8;
            float* p = sM + rl*6;
            p[0]=m2[h]; p[1]=Z2[h]; p[2]=Bv[h]; p[3]=Cv[h]; p[4]=Z1[h]; p[5]=Av[h];
        }
    }
    __syncthreads();
    float wacc = 0.0f;
    if (wn==0 && tig==0){
        #pragma unroll
        for(int h=0;h<2;h++){
            int rl = wm*16 + g + h*8;
            const float* p = sM + rl*6;
            float om=p[0], oZ2=p[1], oB=p[2], oC=p[3], oZ1=p[4], oA=p[5];
            float nm = fmaxf(m2[h], om);
            float c = ex2(m2[h]-nm), d = ex2(om-nm);
            float Z2m = Z2[h]*c + oZ2*d;
            float Bm  = Bv[h]*c*c + oB*d*d;
            float Cm  = Cv[h]*c + oC*d;
            float Z1m = Z1[h] + oZ1;
            float Am  = Av[h] + oA;
            float i1 = 1.0f/Z1m, i2 = 1.0f/Z2m;
            float loss = Am*i1*i1 - 2.0f*Cm*i1*i2 + Bm*i2*i2;
            wacc += wts[b*NPTS + i0 + rl] * loss;
        }
    }
    #pragma unroll
    for(int off=16; off>=1; off>>=1) wacc += __shfl_xor_sync(~0u, wacc, off);
    if (wn==0 && lane==0) sR[wm] = wacc;
    __syncthreads();
    if (tid==0)
        g_partial[b*NIT + blockIdx.x] = (sR[0]+sR[1]) + (sR[2]+sR[3]);
}

// ---------------------------------------------------------------------------
__global__ void reduce_kernel(float* __restrict__ out)
{
    int b    = threadIdx.x >> 5;
    int lane = threadIdx.x & 31;
    float s = g_partial[b*NIT + lane] + g_partial[b*NIT + 32 + lane];
    #pragma unroll
    for(int off=16; off>=1; off>>=1) s += __shfl_xor_sync(~0u, s, off);
    if (lane==0) out[b] = s;
}

// ---------------------------------------------------------------------------
extern "C" void kernel_launch(void* const* d_in, const int* in_sizes, int n_in,
                              void* d_out, int out_size)
{
    const float* pts = (const float*)d_in[0];
    const float* wts = (const float*)d_in[1];
    const float* f1  = (const float*)d_in[2];
    const float* f2  = (const float*)d_in[3];
    float* out = (float*)d_out;

    cudaFuncSetAttribute(loss_kernel, cudaFuncAttributeMaxDynamicSharedMemorySize, SMEM_TOTAL);
    prep_kernel<<<(BATCH*NPTS)/8, 256>>>(pts, f1, f2);
    dim3 grid(NIT, BATCH);
    loss_kernel<<<grid, 256, SMEM_TOTAL>>>(wts);
    reduce_kernel<<<1, 128>>>(out);
}